// round 15
// baseline (speedup 1.0000x reference)
#include <cuda_runtime.h>
#include <cstdint>

// FullTensorProduct, N=4096 rows, MUL=64.
// Per row: a0=in1[:64], a1=in1[64:256] as (64,3); b0,b1 from in2.
// out row (45056 floats):
//   [0,4096)      c000[u*64+v]        = a0[u]*b0[v]
//   [4096,8192)   c110[u*64+v]        = dot(a1[u],b1[v]) / sqrt(3)
//   [8192,20480)  c011[(u*64+v)*3+j]  = a0[u]*b1[v][j]
//   [20480,32768) c101[(u*64+v)*3+i]  = a1[u][i]*b0[v]
//   [32768,45056) c111[(u*64+v)*3+k]  = cross(a1[u],b1[v])[k] / sqrt(2)
//
// FINAL (champion, 102.9us / DRAM 81.4%):
//   grid=4096 (1 row/CTA), 256 threads, 2x45KB smem double buffer,
//   per chunk: compute 16 u's -> 5-piece cp.async.bulk commit (L2
//   evict_first; zero-reuse 738MB stream), wait_group.read 1 ring.
// Measured-flat/worse alternatives: finer chunks (R4/R10), persistent
// (R5/R7), output-contiguous chunks (R8), 2 rows/CTA (R9). DRAM pins at
// ~81% = write-path ceiling for this pattern; dirty-L2 drain past kernel
// end confirms end-to-end write saturation.

constexpr int ROW_IN  = 256;
constexpr int ROW_OUT = 45056;
constexpr int CHUNK_FLOATS = 11264;              // 16 u's = 45056 B
constexpr float INV_SQRT3 = 0.57735026918962576451f;
constexpr float INV_SQRT2 = 0.70710678118654752440f;

__device__ __forceinline__ uint32_t smem_u32(const void* p) {
    uint32_t r;
    asm("{ .reg .u64 t; cvta.to.shared.u64 t, %1; cvt.u32.u64 %0, t; }"
        : "=r"(r) : "l"(p));
    return r;
}

__device__ __forceinline__ uint64_t evict_first_policy() {
    uint64_t pol;
    asm("createpolicy.fractional.L2::evict_first.b64 %0, 1.0;" : "=l"(pol));
    return pol;
}

__device__ __forceinline__ void bulk_store(void* gptr, uint32_t saddr,
                                           uint32_t bytes, uint64_t pol) {
    asm volatile(
        "cp.async.bulk.global.shared::cta.bulk_group.L2::cache_hint "
        "[%0], [%1], %2, %3;"
        :: "l"(gptr), "r"(saddr), "r"(bytes), "l"(pol) : "memory");
}

__global__ __launch_bounds__(256, 2)
void ftp_kernel(const float* __restrict__ in1,
                const float* __restrict__ in2,
                float* __restrict__ out)
{
    __shared__ __align__(16) float a0[64], b0[64];
    __shared__ __align__(16) float a1x[64], a1y[64], a1z[64];
    __shared__ __align__(16) float b1x[64], b1y[64], b1z[64];
    extern __shared__ __align__(16) float buf[];  // 2 * CHUNK_FLOATS

    const int row = blockIdx.x;
    const int t   = threadIdx.x;

    // Stage inputs: 256 floats per operand, a1/b1 split into x/y/z planes.
    {
        const float v1 = in1[(size_t)row * ROW_IN + t];
        const float v2 = in2[(size_t)row * ROW_IN + t];
        if (t < 64) {
            a0[t] = v1; b0[t] = v2;
        } else {
            int idx = t - 64;
            int u = idx / 3;
            int c = idx - 3 * u;
            if (c == 0)      { a1x[u] = v1; b1x[u] = v2; }
            else if (c == 1) { a1y[u] = v1; b1y[u] = v2; }
            else             { a1z[u] = v1; b1z[u] = v2; }
        }
    }
    __syncthreads();

    // b-side quads fixed per thread across all 4 chunks (s = t & 15).
    const int s = t & 15;
    const float4 b  = ((const float4*)b0)[s];
    const float4 bx = ((const float4*)b1x)[s];
    const float4 by = ((const float4*)b1y)[s];
    const float4 bz = ((const float4*)b1z)[s];

    float* orow = out + (size_t)row * ROW_OUT;
    const uint64_t pol = evict_first_policy();   // hoisted (zero-reuse stream)

    #pragma unroll
    for (int k = 0; k < 4; ++k) {
        float* B = buf + (k & 1) * CHUNK_FLOATS;

        if (k >= 2) {
            // Buffer reuse: wait until TMA finished READING the k-2 chunk.
            if (t == 0)
                asm volatile("cp.async.bulk.wait_group.read 1;" ::: "memory");
            __syncthreads();
        }

        const int u = (k << 4) + (t >> 4);
        const float a  = a0[u];
        const float ax = a1x[u], ay = a1y[u], az = a1z[u];

        float4* B000 = (float4*)(B);            // 256 float4
        float4* B110 = (float4*)(B + 1024);     // 256 float4
        float4* B011 = (float4*)(B + 2048);     // 768 float4
        float4* B101 = (float4*)(B + 5120);     // 768 float4
        float4* B111 = (float4*)(B + 8192);     // 768 float4

        // c000
        B000[t] = make_float4(a * b.x, a * b.y, a * b.z, a * b.w);

        // c110
        {
            float4 r;
            r.x = (ax * bx.x + ay * by.x + az * bz.x) * INV_SQRT3;
            r.y = (ax * bx.y + ay * by.y + az * bz.y) * INV_SQRT3;
            r.z = (ax * bx.z + ay * by.z + az * bz.z) * INV_SQRT3;
            r.w = (ax * bx.w + ay * by.w + az * bz.w) * INV_SQRT3;
            B110[t] = r;
        }

        // c011: a0[u]*b1[v][j], j fastest — 12 floats per thread
        B011[3*t + 0] = make_float4(a*bx.x, a*by.x, a*bz.x, a*bx.y);
        B011[3*t + 1] = make_float4(a*by.y, a*bz.y, a*bx.z, a*by.z);
        B011[3*t + 2] = make_float4(a*bz.z, a*bx.w, a*by.w, a*bz.w);

        // c101: a1[u][i]*b0[v], i fastest
        B101[3*t + 0] = make_float4(ax*b.x, ay*b.x, az*b.x, ax*b.y);
        B101[3*t + 1] = make_float4(ay*b.y, az*b.y, ax*b.z, ay*b.z);
        B101[3*t + 2] = make_float4(az*b.z, ax*b.w, ay*b.w, az*b.w);

        // c111: cross(a1[u], b1[v]) / sqrt(2), k fastest
        {
            const float cx0 = (ay*bz.x - az*by.x) * INV_SQRT2;
            const float cy0 = (az*bx.x - ax*bz.x) * INV_SQRT2;
            const float cz0 = (ax*by.x - ay*bx.x) * INV_SQRT2;
            const float cx1 = (ay*bz.y - az*by.y) * INV_SQRT2;
            const float cy1 = (az*bx.y - ax*bz.y) * INV_SQRT2;
            const float cz1 = (ax*by.y - ay*bx.y) * INV_SQRT2;
            const float cx2 = (ay*bz.z - az*by.z) * INV_SQRT2;
            const float cy2 = (az*bx.z - ax*bz.z) * INV_SQRT2;
            const float cz2 = (ax*by.z - ay*bx.z) * INV_SQRT2;
            const float cx3 = (ay*bz.w - az*by.w) * INV_SQRT2;
            const float cy3 = (az*bx.w - ax*bz.w) * INV_SQRT2;
            const float cz3 = (ax*by.w - ay*bx.w) * INV_SQRT2;
            B111[3*t + 0] = make_float4(cx0, cy0, cz0, cx1);
            B111[3*t + 1] = make_float4(cy1, cz1, cx2, cy2);
            B111[3*t + 2] = make_float4(cz2, cx3, cy3, cz3);
        }

        __syncthreads();

        if (t == 0) {
            asm volatile("fence.proxy.async.shared::cta;" ::: "memory");
            const uint32_t sb = smem_u32(B);
            // Large contiguous pieces first: TMA ramps on long runs.
            bulk_store(orow +  8192 + 3*(k << 10), sb +  8192, 12288, pol);
            bulk_store(orow + 20480 + 3*(k << 10), sb + 20480, 12288, pol);
            bulk_store(orow + 32768 + 3*(k << 10), sb + 32768, 12288, pol);
            bulk_store(orow +     0 + (k << 10),   sb +     0,  4096, pol);
            bulk_store(orow +  4096 + (k << 10),   sb +  4096,  4096, pol);
            asm volatile("cp.async.bulk.commit_group;" ::: "memory");
        }
    }

    // Drain before exit (smem lifetime / visibility).
    if (t == 0)
        asm volatile("cp.async.bulk.wait_group.read 0;" ::: "memory");
}

extern "C" void kernel_launch(void* const* d_in, const int* in_sizes, int n_in,
                              void* d_out, int out_size)
{
    const float* in1 = (const float*)d_in[0];
    const float* in2 = (const float*)d_in[1];
    float* out = (float*)d_out;
    const int N = in_sizes[0] / ROW_IN;   // 4096 rows

    const int dyn_smem = 2 * CHUNK_FLOATS * (int)sizeof(float);  // 90112 B
    cudaFuncSetAttribute(ftp_kernel, cudaFuncAttributeMaxDynamicSharedMemorySize, dyn_smem);
    ftp_kernel<<<N, 256, dyn_smem>>>(in1, in2, out);
}

// round 16
// speedup vs baseline: 1.0028x; 1.0028x over previous
#include <cuda_runtime.h>
#include <cstdint>

// FullTensorProduct, N=4096 rows, MUL=64.
// Per row: a0=in1[:64], a1=in1[64:256] as (64,3); b0,b1 from in2.
// out row (45056 floats):
//   [0,4096)      c000[u*64+v]        = a0[u]*b0[v]
//   [4096,8192)   c110[u*64+v]        = dot(a1[u],b1[v]) / sqrt(3)
//   [8192,20480)  c011[(u*64+v)*3+j]  = a0[u]*b1[v][j]
//   [20480,32768) c101[(u*64+v)*3+i]  = a1[u][i]*b0[v]
//   [32768,45056) c111[(u*64+v)*3+k]  = cross(a1[u],b1[v])[k] / sqrt(2)
//
// FINAL champion (102.9us, reproduced twice bit-identically; DRAM 81%):
//   grid=4096 (1 row/CTA), 256 threads, 2x45KB smem double buffer,
//   per chunk: compute 16 u's -> 5-piece cp.async.bulk commit with L2
//   evict_first (zero-reuse 738MB stream), wait_group.read 1 ring.
// Wins: TMA bulk stores (178->109us, LSU/L1 off the store path);
//       evict_first (109->103us).
// Measured-flat/worse: finer chunks (R4/R10), persistent (R5/R7),
//       contiguous chunks (R8), 2 rows/CTA (R9). DRAM pins at ~81% =
//       HBM3e write-path ceiling for streaming stores on sm_103a;
//       effective wallclock BW ~7.2TB/s (~90% of spec).

constexpr int ROW_IN  = 256;
constexpr int ROW_OUT = 45056;
constexpr int CHUNK_FLOATS = 11264;              // 16 u's = 45056 B
constexpr float INV_SQRT3 = 0.57735026918962576451f;
constexpr float INV_SQRT2 = 0.70710678118654752440f;

__device__ __forceinline__ uint32_t smem_u32(const void* p) {
    uint32_t r;
    asm("{ .reg .u64 t; cvta.to.shared.u64 t, %1; cvt.u32.u64 %0, t; }"
        : "=r"(r) : "l"(p));
    return r;
}

__device__ __forceinline__ uint64_t evict_first_policy() {
    uint64_t pol;
    asm("createpolicy.fractional.L2::evict_first.b64 %0, 1.0;" : "=l"(pol));
    return pol;
}

__device__ __forceinline__ void bulk_store(void* gptr, uint32_t saddr,
                                           uint32_t bytes, uint64_t pol) {
    asm volatile(
        "cp.async.bulk.global.shared::cta.bulk_group.L2::cache_hint "
        "[%0], [%1], %2, %3;"
        :: "l"(gptr), "r"(saddr), "r"(bytes), "l"(pol) : "memory");
}

__global__ __launch_bounds__(256, 2)
void ftp_kernel(const float* __restrict__ in1,
                const float* __restrict__ in2,
                float* __restrict__ out)
{
    __shared__ __align__(16) float a0[64], b0[64];
    __shared__ __align__(16) float a1x[64], a1y[64], a1z[64];
    __shared__ __align__(16) float b1x[64], b1y[64], b1z[64];
    extern __shared__ __align__(16) float buf[];  // 2 * CHUNK_FLOATS

    const int row = blockIdx.x;
    const int t   = threadIdx.x;

    // Stage inputs: 256 floats per operand, a1/b1 split into x/y/z planes.
    {
        const float v1 = in1[(size_t)row * ROW_IN + t];
        const float v2 = in2[(size_t)row * ROW_IN + t];
        if (t < 64) {
            a0[t] = v1; b0[t] = v2;
        } else {
            int idx = t - 64;
            int u = idx / 3;
            int c = idx - 3 * u;
            if (c == 0)      { a1x[u] = v1; b1x[u] = v2; }
            else if (c == 1) { a1y[u] = v1; b1y[u] = v2; }
            else             { a1z[u] = v1; b1z[u] = v2; }
        }
    }
    __syncthreads();

    // b-side quads fixed per thread across all 4 chunks (s = t & 15).
    const int s = t & 15;
    const float4 b  = ((const float4*)b0)[s];
    const float4 bx = ((const float4*)b1x)[s];
    const float4 by = ((const float4*)b1y)[s];
    const float4 bz = ((const float4*)b1z)[s];

    float* orow = out + (size_t)row * ROW_OUT;
    const uint64_t pol = evict_first_policy();   // hoisted (zero-reuse stream)

    #pragma unroll
    for (int k = 0; k < 4; ++k) {
        float* B = buf + (k & 1) * CHUNK_FLOATS;

        if (k >= 2) {
            // Buffer reuse: wait until TMA finished READING the k-2 chunk.
            if (t == 0)
                asm volatile("cp.async.bulk.wait_group.read 1;" ::: "memory");
            __syncthreads();
        }

        const int u = (k << 4) + (t >> 4);
        const float a  = a0[u];
        const float ax = a1x[u], ay = a1y[u], az = a1z[u];

        float4* B000 = (float4*)(B);            // 256 float4
        float4* B110 = (float4*)(B + 1024);     // 256 float4
        float4* B011 = (float4*)(B + 2048);     // 768 float4
        float4* B101 = (float4*)(B + 5120);     // 768 float4
        float4* B111 = (float4*)(B + 8192);     // 768 float4

        // c000
        B000[t] = make_float4(a * b.x, a * b.y, a * b.z, a * b.w);

        // c110
        {
            float4 r;
            r.x = (ax * bx.x + ay * by.x + az * bz.x) * INV_SQRT3;
            r.y = (ax * bx.y + ay * by.y + az * bz.y) * INV_SQRT3;
            r.z = (ax * bx.z + ay * by.z + az * bz.z) * INV_SQRT3;
            r.w = (ax * bx.w + ay * by.w + az * bz.w) * INV_SQRT3;
            B110[t] = r;
        }

        // c011: a0[u]*b1[v][j], j fastest — 12 floats per thread
        B011[3*t + 0] = make_float4(a*bx.x, a*by.x, a*bz.x, a*bx.y);
        B011[3*t + 1] = make_float4(a*by.y, a*bz.y, a*bx.z, a*by.z);
        B011[3*t + 2] = make_float4(a*bz.z, a*bx.w, a*by.w, a*bz.w);

        // c101: a1[u][i]*b0[v], i fastest
        B101[3*t + 0] = make_float4(ax*b.x, ay*b.x, az*b.x, ax*b.y);
        B101[3*t + 1] = make_float4(ay*b.y, az*b.y, ax*b.z, ay*b.z);
        B101[3*t + 2] = make_float4(az*b.z, ax*b.w, ay*b.w, az*b.w);

        // c111: cross(a1[u], b1[v]) / sqrt(2), k fastest
        {
            const float cx0 = (ay*bz.x - az*by.x) * INV_SQRT2;
            const float cy0 = (az*bx.x - ax*bz.x) * INV_SQRT2;
            const float cz0 = (ax*by.x - ay*bx.x) * INV_SQRT2;
            const float cx1 = (ay*bz.y - az*by.y) * INV_SQRT2;
            const float cy1 = (az*bx.y - ax*bz.y) * INV_SQRT2;
            const float cz1 = (ax*by.y - ay*bx.y) * INV_SQRT2;
            const float cx2 = (ay*bz.z - az*by.z) * INV_SQRT2;
            const float cy2 = (az*bx.z - ax*bz.z) * INV_SQRT2;
            const float cz2 = (ax*by.z - ay*bx.z) * INV_SQRT2;
            const float cx3 = (ay*bz.w - az*by.w) * INV_SQRT2;
            const float cy3 = (az*bx.w - ax*bz.w) * INV_SQRT2;
            const float cz3 = (ax*by.w - ay*bx.w) * INV_SQRT2;
            B111[3*t + 0] = make_float4(cx0, cy0, cz0, cx1);
            B111[3*t + 1] = make_float4(cy1, cz1, cx2, cy2);
            B111[3*t + 2] = make_float4(cz2, cx3, cy3, cz3);
        }

        __syncthreads();

        if (t == 0) {
            asm volatile("fence.proxy.async.shared::cta;" ::: "memory");
            const uint32_t sb = smem_u32(B);
            // Large contiguous pieces first: TMA ramps on long runs.
            bulk_store(orow +  8192 + 3*(k << 10), sb +  8192, 12288, pol);
            bulk_store(orow + 20480 + 3*(k << 10), sb + 20480, 12288, pol);
            bulk_store(orow + 32768 + 3*(k << 10), sb + 32768, 12288, pol);
            bulk_store(orow +     0 + (k << 10),   sb +     0,  4096, pol);
            bulk_store(orow +  4096 + (k << 10),   sb +  4096,  4096, pol);
            asm volatile("cp.async.bulk.commit_group;" ::: "memory");
        }
    }

    // Drain before exit (smem lifetime / visibility).
    if (t == 0)
        asm volatile("cp.async.bulk.wait_group.read 0;" ::: "memory");
}

extern "C" void kernel_launch(void* const* d_in, const int* in_sizes, int n_in,
                              void* d_out, int out_size)
{
    const float* in1 = (const float*)d_in[0];
    const float* in2 = (const float*)d_in[1];
    float* out = (float*)d_out;
    const int N = in_sizes[0] / ROW_IN;   // 4096 rows

    const int dyn_smem = 2 * CHUNK_FLOATS * (int)sizeof(float);  // 90112 B
    cudaFuncSetAttribute(ftp_kernel, cudaFuncAttributeMaxDynamicSharedMemorySize, dyn_smem);
    ftp_kernel<<<N, 256, dyn_smem>>>(in1, in2, out);
}